// round 13
// baseline (speedup 1.0000x reference)
#include <cuda_runtime.h>
#include <cuda_bf16.h>

// YOLOv3 loss, sm_103a — R8: INVERSE MAPPING.
// Anchors form a regular grid (centers (col+0.5)*stride, 3 fixed sizes), so
// for each (box, type) we enumerate only the tiny cell rectangle where
// IoU>=0.5 is possible, after pruning infeasible types via
// 3*min(aw,bw)*min(ah,bh) >= aw*ah + bw*bh. Positives (~0.3% of anchors) are
// deduped into a worklist and processed exactly. Deletes the O(B*A*M) loop.
// Single kernel: spin-barrier between phases (all blocks co-resident).

#define NUM_CLASSES 80
#define NA 3
#define MAXB 64
#define TPB 256
#define MAXLIST 65536
#define MASK_WORDS 16384   // supports up to 512k (image,anchor) ids

__device__ float        g_cls_sum[MAXB];      // all zero-initialized at load;
__device__ float        g_reg_sum[MAXB];      // self-reset each call
__device__ float        g_npos[MAXB];
__device__ unsigned int g_done;
__device__ unsigned int g_done2;
__device__ int          g_cnt;
__device__ int          g_list[MAXLIST];
__device__ unsigned int g_mask[MASK_WORDS];

__device__ __forceinline__ float sigmoidf_fast(float x) {
    return 1.0f / (1.0f + __expf(-x));
}

__global__ void __launch_bounds__(TPB)
yolo_loss_inv(const float* __restrict__ pred,
              const float* __restrict__ ann,
              const float* __restrict__ anchors,
              float* __restrict__ out,
              int A, int G2, int G, int M, int B) {
    const int tid  = threadIdx.x;
    const int nb   = gridDim.x;
    const int wpb  = TPB / 32;
    const float stride = 2.0f * __ldg(&anchors[0]);   // cx(col 0) = 0.5*stride

    // ================= phase 1: inverse-map candidates =================
    // one warp per (image, box)
    const int lane = tid & 31;
    for (int item = blockIdx.x * wpb + (tid >> 5); item < B * M; item += nb * wpb) {
        const int b = item / M, m = item % M;
        const float* bm = ann + (size_t)(b * M + m) * 5;
        float bx = bm[0], by = bm[1], bw = bm[2], bh = bm[3], cl = bm[4];
        if (cl == -1.0f) continue;                    // padded box
        const float bx2 = bx + bw, by2 = by + bh, am = bw * bh;

        for (int t = 0; t < NA; t++) {
            const float aw = __ldg(&anchors[(size_t)t * G2 * 4 + 2]);
            const float ah = __ldg(&anchors[(size_t)t * G2 * 4 + 3]);
            const float areaA = aw * ah;
            // feasibility: max possible inter = min(aw,bw)*min(ah,bh)
            if (3.0f * fminf(aw, bw) * fminf(ah, bh) < areaA + am) continue;

            const float hw = 0.5f * aw, hh = 0.5f * ah;
            // cells where overlap is possible: |center offset| < (aw+bw)/2 etc.
            // generous ±1 margin; exact test inside.
            int c0 = max(0,     (int)floorf((bx  - hw) / stride - 0.5f) - 1);
            int c1 = min(G - 1, (int)ceilf ((bx2 + hw) / stride - 0.5f) + 1);
            int r0 = max(0,     (int)floorf((by  - hh) / stride - 0.5f) - 1);
            int r1 = min(G - 1, (int)ceilf ((by2 + hh) / stride - 0.5f) + 1);
            if (c1 < c0 || r1 < r0) continue;
            const int W = c1 - c0 + 1;
            const int n = W * (r1 - r0 + 1);

            for (int i = lane; i < n; i += 32) {
                const int col = c0 + i % W;
                const int row = r0 + i / W;
                const float ax = ((float)col + 0.5f) * stride;
                const float ay = ((float)row + 0.5f) * stride;
                float iw = fminf(ax + hw, bx2) - fmaxf(ax - hw, bx);
                float ih = fminf(ay + hh, by2) - fmaxf(ay - hh, by);
                float inter = fmaxf(iw, 0.f) * fmaxf(ih, 0.f);
                // IoU >= 0.5 ⟺ 3*inter >= areaA + am (exact, division-free)
                if (3.0f * inter >= areaA + am) {
                    unsigned gid = (unsigned)(b * A + t * G2 + row * G + col);
                    unsigned bit = 1u << (gid & 31u);
                    unsigned old = atomicOr(&g_mask[gid >> 5], bit);
                    if (!(old & bit)) {               // first claimer appends
                        int pos = atomicAdd(&g_cnt, 1);
                        if (pos < MAXLIST) g_list[pos] = (int)gid;
                    }
                }
            }
        }
    }

    // ---- spin barrier (all nb blocks co-resident: nb <= 148) ----
    __syncthreads();
    if (tid == 0) {
        __threadfence();
        atomicAdd(&g_done, 1u);
        while (*(volatile unsigned int*)&g_done < (unsigned)nb) __nanosleep(64);
    }
    __syncthreads();

    // ================= phase 2: process positives =================
    const int n_ent = min(*(volatile int*)&g_cnt, MAXLIST);
    for (int i = blockIdx.x * TPB + tid; i < n_ent; i += nb * TPB) {
        const int gid = g_list[i];
        const int b = gid / A;
        const int a = gid - b * A;
        const float4 an = __ldg((const float4*)anchors + a);
        const float cx = an.x, cy = an.y, aw = an.z, ah = an.w;
        const float hw = 0.5f * aw, hh = 0.5f * ah, areaA = aw * ah;

        // exact argmax over valid boxes in original order (strict '>', init
        // (-1,1) -> first box wins, first max kept: matches jnp.argmax).
        float bI = -1.f, bU = 1.f;
        float bcx = 0.f, bcy = 0.f, bw_ = 1.f, bh_ = 1.f, bcl = 0.f;
        for (int m = 0; m < M; m++) {
            const float* bm = ann + (size_t)(b * M + m) * 5;
            float cl5 = bm[4];
            if (cl5 == -1.0f) continue;
            float x = bm[0], y = bm[1], w = bm[2], h = bm[3];
            float iw = fminf(cx + hw, x + w) - fmaxf(cx - hw, x);
            float ih = fminf(cy + hh, y + h) - fmaxf(cy - hh, y);
            float inter = fmaxf(iw, 0.f) * fmaxf(ih, 0.f);
            float uni   = areaA + w * h - inter;
            if (inter * bU > bI * uni) {
                bI = inter; bU = uni;
                bcx = x + 0.5f * w; bcy = y + 0.5f * h;
                bw_ = w; bh_ = h; bcl = cl5;
            }
        }

        const float* row = pred + (size_t)gid * (NUM_CLASSES + 5);

        // regression: sum of squared errors (both /denom deferred)
        float r0 = row[0], r1 = row[1], r2 = row[2], r3 = row[3], r4 = row[4];
        float stx = sigmoidf_fast(bcx - cx);
        float sty = sigmoidf_fast(bcy - cy);
        float tw  = __logf(fmaxf(bw_, 1.f) / aw);
        float th  = __logf(fmaxf(bh_, 1.f) / ah);
        float d0 = sigmoidf_fast(r0) - stx;
        float d1 = sigmoidf_fast(r1) - sty;
        float d2 = r2 - tw;
        float d3 = r3 - th;
        float d4 = r4 - 1.0f;
        float regc = d0*d0 + d1*d1 + d2*d2 + d3*d3 + d4*d4;

        // one-hot BCE collapsed: -( log p_t - log(1-p_t) + sum_c log(1-p_c) )
        float acc = 0.f;
        #pragma unroll 8
        for (int c = 0; c < NUM_CLASSES; c++)
            acc += __logf(1.0f - row[5 + c]);
        int t = (int)bcl;
        float pt = row[5 + t];
        float clsc = -(__logf(pt) - __logf(1.0f - pt) + acc);

        atomicAdd(&g_cls_sum[b], clsc);
        atomicAdd(&g_reg_sum[b], regc);
        atomicAdd(&g_npos[b],    1.0f);
    }

    // ---- barrier 2: last block finalizes + resets ----
    __shared__ int s_last;
    __threadfence();
    __syncthreads();
    if (tid == 0) {
        unsigned old = atomicAdd(&g_done2, 1u);
        s_last = (old == (unsigned)nb - 1u);
    }
    __syncthreads();

    if (s_last) {
        // reset only the claimed mask words (duplicate stores are fine)
        for (int i = tid; i < n_ent; i += TPB)
            g_mask[(unsigned)g_list[i] >> 5] = 0u;

        const unsigned full = 0xffffffffu;
        if (tid < 32) {
            float cl = 0.f, rg = 0.f;
            if (tid < B) {
                float n = g_npos[tid];
                float denom = fmaxf(n, 1.f);
                cl = g_cls_sum[tid] / denom;
                rg = (n > 0.f) ? g_reg_sum[tid] / (denom * denom) : 0.f;
                g_cls_sum[tid] = 0.f;
                g_reg_sum[tid] = 0.f;
                g_npos[tid]    = 0.f;
            }
            #pragma unroll
            for (int off = 16; off > 0; off >>= 1) {
                cl += __shfl_down_sync(full, cl, off);
                rg += __shfl_down_sync(full, rg, off);
            }
            if (tid == 0) {
                out[0] = cl / (float)B;
                out[1] = rg / (float)B;
            }
        }
        __syncthreads();
        if (tid == 0) {          // counters last; kernel end orders next replay
            g_cnt   = 0;
            g_done  = 0u;
            g_done2 = 0u;
        }
    }
}

extern "C" void kernel_launch(void* const* d_in, const int* in_sizes, int n_in,
                              void* d_out, int out_size) {
    const float* pred    = (const float*)d_in[0];  // (B, A, 5+C) f32
    const float* ann     = (const float*)d_in[1];  // (B, M, 5) f32
    const float* anchors = (const float*)d_in[2];  // (NA, G, G, 4) f32, type-major
    float* out = (float*)d_out;

    const int A  = in_sizes[2] / 4;
    const int G2 = A / NA;
    const int G  = (int)(sqrtf((float)G2) + 0.5f);
    const int B  = in_sizes[0] / (A * (NUM_CLASSES + 5));
    const int M  = in_sizes[1] / (B * 5);

    // one warp per (image, box); cap blocks at 128 (< 148 SMs) so the spin
    // barrier is deadlock-free (all blocks co-resident in wave 1)
    int nb = (B * M + (TPB / 32) - 1) / (TPB / 32);
    if (nb > 128) nb = 128;
    if (nb < 1)   nb = 1;

    yolo_loss_inv<<<nb, TPB>>>(pred, ann, anchors, out, A, G2, G, M, B);
}

// round 14
// speedup vs baseline: 1.7439x; 1.7439x over previous
#include <cuda_runtime.h>
#include <cuda_bf16.h>

// YOLOv3 loss, sm_103a — R9: separable IoU + per-block box pruning,
// inside the R2 skeleton (1104 blocks, single-kernel last-block finalize).
//
// Block = 256 contiguous anchors of ONE (image, type) plane -> spans <=5 rows.
// Warp 0 prunes boxes by (a) type feasibility: 3*min(aw,bw)*min(ah,bh) >=
// areaA+am (max-possible-inter bound), and (b) y-band overlap with the
// block's rows. Survivors K (typically 1-4 of 24). Then iw[k][col] / ih[k][row]
// tables are built in smem, and the hot test per anchor is K iterations of
// inter = iw*ih; 3*inter >= areaA+am (exact, division-free).
// Pruned boxes can never win the argmax for a positive anchor (feasibility-
// pruned have IoU<0.5 < winner's; y-pruned have inter=0 in this block), so
// the rare cold path argmaxes over the compacted set only.

#define NUM_CLASSES 80
#define NA 3
#define MAXB 64
#define MAXK 32
#define GMAX 96          // max grid dim supported by smem tables (G=76 here)
#define NRMAX 8          // max rows a 256-anchor chunk can span (<=5 for G=76)
#define TPB 256

__device__ float        g_cls_sum[MAXB];   // zero-init at load; self-reset
__device__ float        g_reg_sum[MAXB];
__device__ float        g_npos[MAXB];
__device__ unsigned int g_done;

__device__ __forceinline__ float sigmoidf_fast(float x) {
    return 1.0f / (1.0f + __expf(-x));
}

__global__ void __launch_bounds__(TPB)
yolo_loss_sep(const float* __restrict__ pred,
              const float* __restrict__ ann,
              const float* __restrict__ anchors,
              float* __restrict__ out,
              int A, int G2, int G, int M, int B) {
    __shared__ float4 s_box[MAXK];          // bx1,by1,bx2,by2 (survivors)
    __shared__ float4 s_aux[MAXK];          // cx,cy,w,h (original values)
    __shared__ float  s_cl[MAXK];
    __shared__ float  s_thr[MAXK];          // areaA + am
    __shared__ float  s_iw[MAXK * GMAX];    // clamped overlap width per col
    __shared__ float  s_ih[MAXK * NRMAX];   // clamped overlap height per row
    __shared__ int    s_cnt;
    __shared__ int    s_last;

    const int tid = threadIdx.x;
    const int bt  = blockIdx.y;             // (image, type)
    const int b   = bt / NA;
    const int t   = bt - b * NA;

    const float stride = 2.0f * __ldg(&anchors[0]);       // cx(col0)=0.5*stride
    const float aw = __ldg(&anchors[(size_t)t * G2 * 4 + 2]);
    const float ah = __ldg(&anchors[(size_t)t * G2 * 4 + 3]);
    const float hw = 0.5f * aw, hh = 0.5f * ah;
    const float areaA = aw * ah;

    // this block's anchor range within the (b,t) plane, and its row band
    const int a0 = blockIdx.x * TPB;
    const int a1 = min(a0 + TPB - 1, G2 - 1);
    const int r0 = a0 / G;
    const int r1 = a1 / G;
    const int nrows = r1 - r0 + 1;          // <= 5 for G=76

    // ---- warp 0: prune + compact boxes ----
    if (tid < 32) {
        bool  keep = false;
        float x = 0.f, y = 0.f, w = 0.f, h = 0.f, cl = -1.f, am = 0.f;
        if (tid < M) {
            const float* bm = ann + (size_t)(b * M + tid) * 5;
            x = bm[0]; y = bm[1]; w = bm[2]; h = bm[3]; cl = bm[4];
            if (cl != -1.0f) {
                am = w * h;
                // (a) type feasibility: inter <= min widths * min heights
                bool feas = 3.0f * fminf(aw, w) * fminf(ah, h) >= areaA + am;
                // (b) y-band overlap (closed ineq -> conservative superset)
                float ay_min = ((float)r0 + 0.5f) * stride;
                float ay_max = ((float)r1 + 0.5f) * stride;
                bool yov = (ay_min <= (y + h) + hh) && (ay_max >= y - hh);
                keep = feas && yov;
            }
        }
        unsigned mask = __ballot_sync(0xffffffffu, keep);
        if (keep) {
            int k = __popc(mask & ((1u << tid) - 1u));
            s_box[k] = make_float4(x, y, x + w, y + h);
            s_aux[k] = make_float4(x + 0.5f * w, y + 0.5f * h, w, h);
            s_cl[k]  = cl;
            s_thr[k] = areaA + am;
        }
        if (tid == 0) s_cnt = __popc(mask);
    }
    __syncthreads();

    const int K = s_cnt;

    // ---- build separable tables (trivial: K*G + K*nrows entries total) ----
    for (int i = tid; i < K * G; i += TPB) {
        int k = i / G, col = i - k * G;
        float ax = ((float)col + 0.5f) * stride;     // bitwise == anchors array
        float4 c = s_box[k];
        float iw = fminf(ax + hw, c.z) - fmaxf(ax - hw, c.x);
        s_iw[k * GMAX + col] = fmaxf(iw, 0.f);
    }
    for (int i = tid; i < K * nrows; i += TPB) {
        int k = i / nrows, ri = i - k * nrows;
        float ay = ((float)(r0 + ri) + 0.5f) * stride;
        float4 c = s_box[k];
        float ih = fminf(ay + hh, c.w) - fmaxf(ay - hh, c.y);
        s_ih[k * NRMAX + ri] = fmaxf(ih, 0.f);
    }
    __syncthreads();

    const int a = a0 + tid;                 // anchor index within (b,t) plane
    float clsc = 0.f, regc = 0.f, posc = 0.f;

    if (a < G2) {
        const int r  = a / G;
        const int c  = a - r * G;
        const int ri = r - r0;

        // ---- HOT: K iters of 2 LDS + FMUL + compare ----
        bool hit = false;
        for (int k = 0; k < K; k++) {
            float inter = s_iw[k * GMAX + c] * s_ih[k * NRMAX + ri];
            hit |= (3.0f * inter >= s_thr[k]);   // IoU>=0.5, exact & div-free
        }

        // ---- COLD (~0.3%): exact argmax over compacted set + losses ----
        if (hit) {
            posc = 1.f;
            const float ax  = ((float)c + 0.5f) * stride;
            const float ay  = ((float)r + 0.5f) * stride;
            const float ax1 = ax - hw, ay1 = ay - hh;
            const float ax2 = ax + hw, ay2 = ay + hh;

            // (inter,union) cross-mult argmax; strict '>' keeps first max.
            float bI = -1.f, bU = 1.f;
            int   bk = 0;
            for (int k = 0; k < K; k++) {
                float4 cb = s_box[k];
                float iw = fmaxf(fminf(ax2, cb.z) - fmaxf(ax1, cb.x), 0.f);
                float ih = fmaxf(fminf(ay2, cb.w) - fmaxf(ay1, cb.y), 0.f);
                float inter = iw * ih;
                float uni   = s_thr[k] - inter;          // areaA+am-inter
                if (inter * bU > bI * uni) { bI = inter; bU = uni; bk = k; }
            }

            const float4 bx = s_aux[bk];     // cx,cy,w,h
            const float* row = pred +
                (size_t)((b * NA + t) * G2 + a) * (NUM_CLASSES + 5);

            // regression: sum of squared errors (both /denom deferred)
            float r0_ = row[0], r1_ = row[1], r2_ = row[2], r3_ = row[3], r4_ = row[4];
            float stx = sigmoidf_fast(bx.x - ax);
            float sty = sigmoidf_fast(bx.y - ay);
            float tw  = __logf(fmaxf(bx.z, 1.f) / aw);
            float th  = __logf(fmaxf(bx.w, 1.f) / ah);
            float d0 = sigmoidf_fast(r0_) - stx;
            float d1 = sigmoidf_fast(r1_) - sty;
            float d2 = r2_ - tw;
            float d3 = r3_ - th;
            float d4 = r4_ - 1.0f;
            regc = d0*d0 + d1*d1 + d2*d2 + d3*d3 + d4*d4;

            // one-hot BCE collapsed: -( log p_t - log(1-p_t) + Σc log(1-p_c) )
            float acc = 0.f;
            #pragma unroll 8
            for (int cc = 0; cc < NUM_CLASSES; cc++)
                acc += __logf(1.0f - row[5 + cc]);
            int tcl = (int)s_cl[bk];
            float pt = row[5 + tcl];
            clsc = -(__logf(pt) - __logf(1.0f - pt) + acc);
        }
    }

    // ---- warp reduce, one conditional atomic triple per warp ----
    const unsigned full = 0xffffffffu;
    #pragma unroll
    for (int off = 16; off > 0; off >>= 1) {
        clsc += __shfl_down_sync(full, clsc, off);
        regc += __shfl_down_sync(full, regc, off);
        posc += __shfl_down_sync(full, posc, off);
    }
    if ((tid & 31) == 0 && posc > 0.f) {
        atomicAdd(&g_cls_sum[b], clsc);
        atomicAdd(&g_reg_sum[b], regc);
        atomicAdd(&g_npos[b],    posc);
    }

    // ---- last-block finalize (R2 machinery) ----
    __syncthreads();
    if (tid == 0) {
        __threadfence();
        unsigned total = gridDim.x * gridDim.y;
        unsigned old = atomicAdd(&g_done, 1u);
        s_last = (old == total - 1u);
    }
    __syncthreads();

    if (s_last && tid < 32) {
        __threadfence();
        float cl = 0.f, rg = 0.f;
        if (tid < B) {
            float n = g_npos[tid];
            float denom = fmaxf(n, 1.f);
            cl = g_cls_sum[tid] / denom;
            rg = (n > 0.f) ? g_reg_sum[tid] / (denom * denom) : 0.f;
            g_cls_sum[tid] = 0.f;
            g_reg_sum[tid] = 0.f;
            g_npos[tid]    = 0.f;
        }
        #pragma unroll
        for (int off = 16; off > 0; off >>= 1) {
            cl += __shfl_down_sync(full, cl, off);
            rg += __shfl_down_sync(full, rg, off);
        }
        if (tid == 0) {
            out[0] = cl / (float)B;
            out[1] = rg / (float)B;
            g_done = 0u;
        }
    }
}

extern "C" void kernel_launch(void* const* d_in, const int* in_sizes, int n_in,
                              void* d_out, int out_size) {
    const float* pred    = (const float*)d_in[0];  // (B, NA*G2, 5+C) f32
    const float* ann     = (const float*)d_in[1];  // (B, M, 5) f32
    const float* anchors = (const float*)d_in[2];  // (NA, G, G, 4) f32
    float* out = (float*)d_out;

    const int A  = in_sizes[2] / 4;
    const int G2 = A / NA;
    const int G  = (int)(sqrtf((float)G2) + 0.5f);
    const int B  = in_sizes[0] / (A * (NUM_CLASSES + 5));
    const int M  = in_sizes[1] / (B * 5);

    dim3 grid((G2 + TPB - 1) / TPB, B * NA);   // 23 x 48 = 1104 blocks
    yolo_loss_sep<<<grid, TPB>>>(pred, ann, anchors, out, A, G2, G, M, B);
}